// round 5
// baseline (speedup 1.0000x reference)
#include <cuda_runtime.h>
#include <math.h>
#include <stdint.h>

#define BB 8
#define TT 1024
#define CC 192
#define HH 2
#define DKK 96
#define FCC 768
#define LL 6
#define WW 4

// ---------------- scratch (device globals; no allocations) ----------------
__device__ float g_X [BB*CC*TT];
__device__ float g_Xr[BB*CC*TT];          // tf32-rounded copy of X
__device__ float g_Q [BB*CC*TT];          // rounded, pre-scaled
__device__ float g_K [BB*CC*TT];          // rounded
__device__ float g_V [BB*CC*TT];          // rounded
__device__ float g_A [BB*CC*TT];          // rounded attn out
__device__ float g_Y [BB*CC*TT];
__device__ float g_Hf[BB*FCC*TT];         // rounded ffn hidden
__device__ float g_W1t[LL*3*FCC*CC];      // pre-rounded, [l][j][f][c]
__device__ float g_W2t[LL*3*CC*FCC];
__device__ float g_Wqr[LL*CC*CC];
__device__ float g_Wkr[LL*CC*CC];
__device__ float g_Wvr[LL*CC*CC];
__device__ float g_Wor[LL*CC*CC];

static __device__ __forceinline__ float relscale() { return 0.10206207261596577f; } // 1/sqrt(96)

static __device__ __forceinline__ uint32_t f2tf(float f) {
    uint32_t r;
    asm("cvt.rna.tf32.f32 %0, %1;" : "=r"(r) : "f"(f));
    return r;
}
static __device__ __forceinline__ float rndf(float f) { return __uint_as_float(f2tf(f)); }

static __device__ __forceinline__ void mma8(float* c, const uint32_t* a, const uint32_t* b) {
    asm volatile(
        "mma.sync.aligned.m16n8k8.row.col.f32.tf32.tf32.f32 "
        "{%0,%1,%2,%3},{%4,%5,%6,%7},{%8,%9},{%0,%1,%2,%3};"
        : "+f"(c[0]), "+f"(c[1]), "+f"(c[2]), "+f"(c[3])
        : "r"(a[0]), "r"(a[1]), "r"(a[2]), "r"(a[3]), "r"(b[0]), "r"(b[1]));
}

static __device__ __forceinline__ void cpa16(void* s, const void* g) {
    uint32_t sa = (uint32_t)__cvta_generic_to_shared(s);
    asm volatile("cp.async.cg.shared.global [%0], [%1], 16;" :: "r"(sa), "l"(g));
}
#define CP_COMMIT asm volatile("cp.async.commit_group;")
#define CP_WAIT0  asm volatile("cp.async.wait_group 0;")

// ----- stage over one BK=32 chunk; A smem [m][k], B smem [k][n] ------------
template<int MI, int NI>
static __device__ __forceinline__ void stage_mk_kn(
    const uint32_t* sA, int lda, const uint32_t* sB, int ldb, int nofs,
    float (*acc)[NI][4], int wm, int wn, int grp, int qid)
{
#pragma unroll
    for (int ks = 0; ks < 32; ks += 8) {
        uint32_t a[MI][4], b[NI][2];
#pragma unroll
        for (int mi = 0; mi < MI; mi++) {
            const uint32_t* p0 = sA + (wm + mi*16 + grp)*lda + ks + qid;
            a[mi][0] = p0[0]; a[mi][1] = p0[8*lda]; a[mi][2] = p0[4]; a[mi][3] = p0[8*lda + 4];
        }
#pragma unroll
        for (int ni = 0; ni < NI; ni++) {
            const uint32_t* q0 = sB + (ks + qid)*ldb + nofs + wn + ni*8 + grp;
            b[ni][0] = q0[0]; b[ni][1] = q0[4*ldb];
        }
#pragma unroll
        for (int mi = 0; mi < MI; mi++)
#pragma unroll
            for (int ni = 0; ni < NI; ni++)
                mma8(acc[mi][ni], a[mi], b[ni]);
    }
}

// ----- A smem [k][m], B smem [k][n] ----------------------------------------
template<int MI, int NI>
static __device__ __forceinline__ void stage_km_kn(
    const uint32_t* sA, int lda, const uint32_t* sB, int ldb,
    float (*acc)[NI][4], int wm, int wn, int grp, int qid)
{
#pragma unroll
    for (int ks = 0; ks < 32; ks += 8) {
        uint32_t a[MI][4], b[NI][2];
#pragma unroll
        for (int mi = 0; mi < MI; mi++) {
            const uint32_t* p0 = sA + (ks + qid)*lda + wm + mi*16 + grp;
            const uint32_t* p1 = p0 + 4*lda;
            a[mi][0] = p0[0]; a[mi][1] = p0[8]; a[mi][2] = p1[0]; a[mi][3] = p1[8];
        }
#pragma unroll
        for (int ni = 0; ni < NI; ni++) {
            const uint32_t* q0 = sB + (ks + qid)*ldb + wn + ni*8 + grp;
            b[ni][0] = q0[0]; b[ni][1] = q0[4*ldb];
        }
#pragma unroll
        for (int mi = 0; mi < MI; mi++)
#pragma unroll
            for (int ni = 0; ni < NI; ni++)
                mma8(acc[mi][ni], a[mi], b[ni]);
    }
}

// ----- A smem [m][k], B smem [n][k] ----------------------------------------
template<int MI, int NI>
static __device__ __forceinline__ void stage_mk_nk(
    const uint32_t* sA, int lda, const uint32_t* sB, int ldb,
    float (*acc)[NI][4], int wm, int wn, int grp, int qid)
{
#pragma unroll
    for (int ks = 0; ks < 32; ks += 8) {
        uint32_t a[MI][4], b[NI][2];
#pragma unroll
        for (int mi = 0; mi < MI; mi++) {
            const uint32_t* p0 = sA + (wm + mi*16 + grp)*lda + ks + qid;
            a[mi][0] = p0[0]; a[mi][1] = p0[8*lda]; a[mi][2] = p0[4]; a[mi][3] = p0[8*lda + 4];
        }
#pragma unroll
        for (int ni = 0; ni < NI; ni++) {
            const uint32_t* q0 = sB + (wn + ni*8 + grp)*ldb + ks + qid;
            b[ni][0] = q0[0]; b[ni][1] = q0[4];
        }
#pragma unroll
        for (int mi = 0; mi < MI; mi++)
#pragma unroll
            for (int ni = 0; ni < NI; ni++)
                mma8(acc[mi][ni], a[mi], b[ni]);
    }
}

// ===== projection body (double-buffered, raw pre-rounded fills) ============
#define PROJ_SMEM_W (2*64*36 + 2*32*136)
static __device__ __forceinline__ void proj_body(
    const float* __restrict__ W, const float* __restrict__ bias,
    const float* __restrict__ Xb, float* __restrict__ Ob, int o0, int n0,
    uint32_t* sm, float outscale, int roundout)
{
    uint32_t* sA = sm;
    uint32_t* sB = sm + 2*64*36;
    const int tid = threadIdx.x;
    const int lane = tid & 31, w = tid >> 5;
    const int grp = lane >> 2, qid = lane & 3;
    const int wm = (w & 1)*32, wn = (w >> 1)*32;
    float acc[2][4][4] = {};
    const int rA = tid >> 3,  cA = (tid & 7)*4;
    const int rB = tid >> 5,  cB = (tid & 31)*4;

#pragma unroll
    for (int jj = 0; jj < 2; jj++)
        *(uint4*)&sA[(rA + jj*32)*36 + cA] = *(const uint4*)&W[(o0 + rA + jj*32)*CC + cA];
#pragma unroll
    for (int jj = 0; jj < 4; jj++)
        *(uint4*)&sB[(rB + jj*8)*136 + cB] = *(const uint4*)&Xb[(size_t)(rB + jj*8)*TT + n0 + cB];
    __syncthreads();

    const int NK = CC/32;
    for (int k = 0; k < NK; k++) {
        uint4 ra[2], rb[4];
        if (k + 1 < NK) {
            int k0 = (k + 1)*32;
#pragma unroll
            for (int jj = 0; jj < 2; jj++)
                ra[jj] = *(const uint4*)&W[(o0 + rA + jj*32)*CC + k0 + cA];
#pragma unroll
            for (int jj = 0; jj < 4; jj++)
                rb[jj] = *(const uint4*)&Xb[(size_t)(k0 + rB + jj*8)*TT + n0 + cB];
        }
        int cur = k & 1;
        stage_mk_kn<2,4>(sA + cur*64*36, 36, sB + cur*32*136, 136, 0, acc, wm, wn, grp, qid);
        if (k + 1 < NK) {
            int nx = cur ^ 1;
#pragma unroll
            for (int jj = 0; jj < 2; jj++)
                *(uint4*)&sA[nx*64*36 + (rA + jj*32)*36 + cA] = ra[jj];
#pragma unroll
            for (int jj = 0; jj < 4; jj++)
                *(uint4*)&sB[nx*32*136 + (rB + jj*8)*136 + cB] = rb[jj];
            __syncthreads();
        }
    }
#pragma unroll
    for (int mi = 0; mi < 2; mi++) {
        int r0 = o0 + wm + mi*16 + grp;
        float bb0 = bias[r0], bb1 = bias[r0 + 8];
#pragma unroll
        for (int ni = 0; ni < 4; ni++) {
            int c0 = n0 + wn + ni*8 + qid*2;
            float v0 = (acc[mi][ni][0] + bb0)*outscale;
            float v1 = (acc[mi][ni][1] + bb0)*outscale;
            float v2 = (acc[mi][ni][2] + bb1)*outscale;
            float v3 = (acc[mi][ni][3] + bb1)*outscale;
            if (roundout) { v0 = rndf(v0); v1 = rndf(v1); v2 = rndf(v2); v3 = rndf(v3); }
            Ob[(size_t)r0*TT + c0]       = v0;
            Ob[(size_t)r0*TT + c0 + 1]   = v1;
            Ob[(size_t)(r0+8)*TT + c0]   = v2;
            Ob[(size_t)(r0+8)*TT + c0+1] = v3;
        }
    }
}

__global__ void qkv_mma(const float* __restrict__ Wq, const float* __restrict__ bq,
                        const float* __restrict__ Wk, const float* __restrict__ bk,
                        const float* __restrict__ Wv, const float* __restrict__ bv,
                        const float* __restrict__ X,
                        float* __restrict__ Qo, float* __restrict__ Ko, float* __restrict__ Vo)
{
    extern __shared__ uint32_t sm[];
    const int sel = blockIdx.x / 3;
    const int o0  = (blockIdx.x % 3)*64;
    const int n0  = blockIdx.y*128;
    const int b   = blockIdx.z;
    const float* W    = (sel == 0) ? Wq : (sel == 1) ? Wk : Wv;
    const float* bias = (sel == 0) ? bq : (sel == 1) ? bk : bv;
    float* Out        = (sel == 0) ? Qo : (sel == 1) ? Ko : Vo;
    float sc = (sel == 0) ? relscale() : 1.f;
    proj_body(W, bias, X + (size_t)b*CC*TT, Out + (size_t)b*CC*TT, o0, n0, sm, sc, 1);
}

__global__ void proj_mma(const float* __restrict__ W, const float* __restrict__ bias,
                         const float* __restrict__ X, float* __restrict__ Out)
{
    extern __shared__ uint32_t sm[];
    proj_body(W, bias, X + (size_t)blockIdx.z*CC*TT, Out + (size_t)blockIdx.z*CC*TT,
              blockIdx.x*64, blockIdx.y*128, sm, 1.f, 0);
}

// ===== flash attention: fused scores + rel + softmax + PV + rel-v band =====
// smem words: sQ 96*72, sK 96*72, sV 96*68, sP 64*68, + float stats
#define FLASH_SMEM_W (96*72 + 96*72 + 96*68 + 64*68 + 576 + 576 + 128 + 128 + 64 + 64 + 864)
__global__ void __launch_bounds__(256)
flash_k(const float* __restrict__ Q, const float* __restrict__ Kg,
        const float* __restrict__ Vg, const float* __restrict__ erk,
        const float* __restrict__ erv, float* __restrict__ Aout)
{
    extern __shared__ uint32_t sm[];
    uint32_t* sQ = sm;                // [d][t] 96x72
    uint32_t* sK = sQ + 96*72;        // [d][s] 96x72
    uint32_t* sV = sK + 96*72;        // [d][s] 96x68
    uint32_t* sP = sV + 96*68;        // [t][s] 64x68
    float* rl   = (float*)(sP + 64*68);   // [64][9]
    float* bP   = rl + 576;               // [64][9]
    float* pmax = bP + 576;               // [64][2]
    float* psum = pmax + 128;             // [64][2]
    float* mrow = psum + 128;             // [64]
    float* lrow = mrow + 64;              // [64]
    float* sE   = lrow + 64;              // [9][96]

    const int bh = blockIdx.y, b = bh >> 1, h = bh & 1;
    const int t0 = blockIdx.x*64;
    const float* q = Q  + (size_t)(b*CC + h*DKK)*TT;
    const float* k = Kg + (size_t)(b*CC + h*DKK)*TT;
    const float* v = Vg + (size_t)(b*CC + h*DKK)*TT;
    float* aout = Aout + (size_t)(b*CC + h*DKK)*TT;

    const int tid = threadIdx.x;
    const int lane = tid & 31, wq = tid >> 5;
    const int grp = lane >> 2, qid = lane & 3;
    const int mq = wq & 3, nh = wq >> 2;
    const int r0 = mq*16 + grp, r1 = r0 + 8;

    // initial loads: Q(t0), K(0), V(0)
    for (int i = tid; i < 96*16; i += 256) {
        int r = i >> 4, sg = (i & 15)*4;
        cpa16(&sQ[r*72 + sg], &q[(size_t)r*TT + t0 + sg]);
        cpa16(&sK[r*72 + sg], &k[(size_t)r*TT + sg]);
        cpa16(&sV[r*68 + sg], &v[(size_t)r*TT + sg]);
    }
    CP_COMMIT;

    if (tid < 64) { mrow[tid] = -1e30f; lrow[tid] = 0.f; }
    for (int i = tid; i < 576; i += 256) bP[i] = 0.f;
    for (int i = tid; i < 864; i += 256) sE[i] = erv[i];

    CP_WAIT0;
    __syncthreads();

    // rel logits rl[t][m] = sum_d Qs[d][t] * erk[m][d] (Q pre-scaled)
    const float* sQf = (const float*)sQ;
    for (int i = tid; i < 576; i += 256) {
        int t = i / 9, m = i - (i/9)*9;
        float acc = 0.f;
        for (int d = 0; d < 96; d++) acc += sQf[d*72 + t]*erk[m*96 + d];
        rl[t*9 + m] = acc;
    }

    float accO[1][6][4] = {};
    const int NIT = TT/64;
    for (int it = 0; it < NIT; it++) {
        if (it > 0) { CP_WAIT0; }
        __syncthreads();                        // s0: K/V tiles ready, sP free

        float accS[1][4][4] = {};
#pragma unroll
        for (int c = 0; c < 3; c++)
            stage_km_kn<1,4>(sQ + c*32*72, 72, sK + c*32*72, 72, accS, mq*16, nh*32, grp, qid);

        // band rel-k add
#pragma unroll
        for (int ni = 0; ni < 4; ni++) {
            int sl = nh*32 + ni*8 + qid*2;
            int sg = it*64 + sl;
            int o00 = sg - (t0 + r0);
            if (o00 >= -WW && o00 <= WW)       accS[0][ni][0] += rl[r0*9 + o00 + WW];
            if (o00+1 >= -WW && o00+1 <= WW)   accS[0][ni][1] += rl[r0*9 + o00 + 1 + WW];
            int o10 = sg - (t0 + r1);
            if (o10 >= -WW && o10 <= WW)       accS[0][ni][2] += rl[r1*9 + o10 + WW];
            if (o10+1 >= -WW && o10+1 <= WW)   accS[0][ni][3] += rl[r1*9 + o10 + 1 + WW];
        }

        // block row max (partial per nh)
        float v0 = -1e30f, v1 = -1e30f;
#pragma unroll
        for (int ni = 0; ni < 4; ni++) {
            v0 = fmaxf(v0, fmaxf(accS[0][ni][0], accS[0][ni][1]));
            v1 = fmaxf(v1, fmaxf(accS[0][ni][2], accS[0][ni][3]));
        }
        v0 = fmaxf(v0, __shfl_xor_sync(0xffffffffu, v0, 1));
        v0 = fmaxf(v0, __shfl_xor_sync(0xffffffffu, v0, 2));
        v1 = fmaxf(v1, __shfl_xor_sync(0xffffffffu, v1, 1));
        v1 = fmaxf(v1, __shfl_xor_sync(0xffffffffu, v1, 2));
        if (qid == 0) { pmax[r0*2 + nh] = v0; pmax[r1*2 + nh] = v1; }
        __syncthreads();                        // s1

        // prefetch next K (sK free now)
        if (it + 1 < NIT) {
            int s0n = (it + 1)*64;
            for (int i = tid; i < 96*16; i += 256) {
                int r = i >> 4, sg = (i & 15)*4;
                cpa16(&sK[r*72 + sg], &k[(size_t)r*TT + s0n + sg]);
            }
            CP_COMMIT;
        }

        float mb0 = fmaxf(pmax[r0*2], pmax[r0*2 + 1]);
        float mo0 = mrow[r0];
        float mn0 = fmaxf(mo0, mb0);
        float al0 = __expf(mo0 - mn0);
        float mb1 = fmaxf(pmax[r1*2], pmax[r1*2 + 1]);
        float mo1 = mrow[r1];
        float mn1 = fmaxf(mo1, mb1);
        float al1 = __expf(mo1 - mn1);

        float ps0 = 0.f, ps1 = 0.f;
#pragma unroll
        for (int ni = 0; ni < 4; ni++) {
            accS[0][ni][0] = __expf(accS[0][ni][0] - mn0); ps0 += accS[0][ni][0];
            accS[0][ni][1] = __expf(accS[0][ni][1] - mn0); ps0 += accS[0][ni][1];
            accS[0][ni][2] = __expf(accS[0][ni][2] - mn1); ps1 += accS[0][ni][2];
            accS[0][ni][3] = __expf(accS[0][ni][3] - mn1); ps1 += accS[0][ni][3];
        }
        ps0 += __shfl_xor_sync(0xffffffffu, ps0, 1);
        ps0 += __shfl_xor_sync(0xffffffffu, ps0, 2);
        ps1 += __shfl_xor_sync(0xffffffffu, ps1, 1);
        ps1 += __shfl_xor_sync(0xffffffffu, ps1, 2);
        if (qid == 0) { psum[r0*2 + nh] = ps0; psum[r1*2 + nh] = ps1; }
        __syncthreads();                        // s2

        if (tid < 64) {
            int row = tid;
            float mb = fmaxf(pmax[row*2], pmax[row*2 + 1]);
            float mo = mrow[row];
            float mn = fmaxf(mo, mb);
            float al = __expf(mo - mn);
            lrow[row] = lrow[row]*al + psum[row*2] + psum[row*2 + 1];
            mrow[row] = mn;
#pragma unroll
            for (int m = 0; m < 9; m++) bP[row*9 + m] *= al;
        }
        // rescale O accumulators
#pragma unroll
        for (int ni = 0; ni < 6; ni++) {
            accO[0][ni][0] *= al0; accO[0][ni][1] *= al0;
            accO[0][ni][2] *= al1; accO[0][ni][3] *= al1;
        }
        __syncthreads();                        // s3 (bP rescale done)

        // store P tile (tf32) + band accumulation
#pragma unroll
        for (int ni = 0; ni < 4; ni++) {
            int sl = nh*32 + ni*8 + qid*2;
            sP[r0*68 + sl]     = f2tf(accS[0][ni][0]);
            sP[r0*68 + sl + 1] = f2tf(accS[0][ni][1]);
            sP[r1*68 + sl]     = f2tf(accS[0][ni][2]);
            sP[r1*68 + sl + 1] = f2tf(accS[0][ni][3]);
            int sg = it*64 + sl;
            int o00 = sg - (t0 + r0);
            if (o00 >= -WW && o00 <= WW)      bP[r0*9 + o00 + WW]     += accS[0][ni][0];
            if (o00+1 >= -WW && o00+1 <= WW)  bP[r0*9 + o00 + 1 + WW] += accS[0][ni][1];
            int o10 = sg - (t0 + r1);
            if (o10 >= -WW && o10 <= WW)      bP[r1*9 + o10 + WW]     += accS[0][ni][2];
            if (o10+1 >= -WW && o10+1 <= WW)  bP[r1*9 + o10 + 1 + WW] += accS[0][ni][3];
        }
        __syncthreads();                        // s4 (sP ready)

        // O += P * V^T  (A=[t][s] mk, B=[d][s] nk)
#pragma unroll
        for (int c = 0; c < 2; c++)
            stage_mk_nk<1,6>(sP + c*32, 68, sV + c*32, 68, accO, mq*16, nh*48, grp, qid);
        __syncthreads();                        // s5 (sV free)

        if (it + 1 < NIT) {
            int s0n = (it + 1)*64;
            for (int i = tid; i < 96*16; i += 256) {
                int r = i >> 4, sg = (i & 15)*4;
                cpa16(&sV[r*68 + sg], &v[(size_t)r*TT + s0n + sg]);
            }
            CP_COMMIT;
        }
    }

    // epilogue: O = (O + bP * erv) / l, store rounded at [d][t]
    float il0 = 1.f / lrow[r0];
    float il1 = 1.f / lrow[r1];
#pragma unroll
    for (int ni = 0; ni < 6; ni++) {
        int d = nh*48 + ni*8 + qid*2;
        float b00 = 0.f, b01 = 0.f, b10 = 0.f, b11 = 0.f;
#pragma unroll
        for (int m = 0; m < 9; m++) {
            float e0 = sE[m*96 + d], e1 = sE[m*96 + d + 1];
            float p0 = bP[r0*9 + m], p1 = bP[r1*9 + m];
            b00 += p0*e0; b01 += p0*e1; b10 += p1*e0; b11 += p1*e1;
        }
        aout[(size_t)d*TT + t0 + r0]       = rndf((accO[0][ni][0] + b00)*il0);
        aout[(size_t)(d+1)*TT + t0 + r0]   = rndf((accO[0][ni][1] + b01)*il0);
        aout[(size_t)d*TT + t0 + r1]       = rndf((accO[0][ni][2] + b10)*il1);
        aout[(size_t)(d+1)*TT + t0 + r1]   = rndf((accO[0][ni][3] + b11)*il1);
    }
}

// ===== conv3 (DB, raw pre-rounded fills) ====================================
#define CONV_SMEM_W (2*3*64*36 + 2*32*136)
__global__ void conv3_mma(const float* __restrict__ Wt, const float* __restrict__ bias,
                          const float* __restrict__ X, float* __restrict__ Out,
                          int Cout, int Cin, int do_relu, int do_round)
{
    extern __shared__ uint32_t sm[];
    uint32_t* sA = sm;                 // 2 * 3 * 64*36
    uint32_t* sB = sm + 2*3*64*36;     // 2 * 32*136 slab; col = t - t0 + 4
    const int o0 = blockIdx.x*64, t0 = blockIdx.y*128, b = blockIdx.z;
    const float* Xb = X + (size_t)b*Cin*TT;
    float* Ob = Out + (size_t)b*Cout*TT;

    const int tid = threadIdx.x;
    const int lane = tid & 31, w = tid >> 5;
    const int grp = lane >> 2, qid = lane & 3;
    const int wm = (w & 1)*32, wn = (w >> 1)*32;
    float acc[2][4][4] = {};
    const int rS = tid >> 5, cS = (tid & 31)*4;
    const int er = tid >> 1, es = tid & 1;

    auto fill_slab = [&](uint32_t* dst, int c0) {
#pragma unroll
        for (int jj = 0; jj < 4; jj++)
            *(uint4*)&dst[(rS + jj*8)*136 + 4 + cS] =
                *(const uint4*)&Xb[(size_t)(c0 + rS + jj*8)*TT + t0 + cS];
        if (tid < 64) {
            int t = es ? (t0 + 128) : (t0 - 1);
            int col = es ? 132 : 3;
            float vv = (t >= 0 && t < TT) ? Xb[(size_t)(c0 + er)*TT + t] : 0.f;
            dst[er*136 + col] = __float_as_uint(vv);
        }
    };
    auto fill_w = [&](uint32_t* dst, int c0) {
#pragma unroll
        for (int jj = 0; jj < 6; jj++) {
            int i = tid + jj*256;
            int j = i >> 9, r = (i >> 3) & 63, c4 = (i & 7)*4;
            *(uint4*)&dst[j*2304 + r*36 + c4] =
                *(const uint4*)&Wt[((size_t)j*Cout + o0 + r)*Cin + c0 + c4];
        }
    };

    fill_slab(sB, 0);
    fill_w(sA, 0);
    __syncthreads();

    const int NK = Cin/32;
    for (int kc = 0; kc < NK; kc++) {
        uint4 rx[4]; uint32_t re = 0; uint4 rw[6];
        if (kc + 1 < NK) {
            int c0 = (kc + 1)*32;
#pragma unroll
            for (int jj = 0; jj < 4; jj++)
                rx[jj] = *(const uint4*)&Xb[(size_t)(c0 + rS + jj*8)*TT + t0 + cS];
            if (tid < 64) {
                int t = es ? (t0 + 128) : (t0 - 1);
                float vv = (t >= 0 && t < TT) ? Xb[(size_t)(c0 + er)*TT + t] : 0.f;
                re = __float_as_uint(vv);
            }
#pragma unroll
            for (int jj = 0; jj < 6; jj++) {
                int i = tid + jj*256;
                int j = i >> 9, r = (i >> 3) & 63, c4 = (i & 7)*4;
                rw[jj] = *(const uint4*)&Wt[((size_t)j*Cout + o0 + r)*Cin + c0 + c4];
            }
        }
        int cur = kc & 1;
#pragma unroll
        for (int j = 0; j < 3; j++)
            stage_mk_kn<2,4>(sA + cur*3*2304 + j*2304, 36, sB + cur*32*136, 136,
                             j + 3, acc, wm, wn, grp, qid);
        if (kc + 1 < NK) {
            int nx = cur ^ 1;
#pragma unroll
            for (int jj = 0; jj < 4; jj++)
                *(uint4*)&sB[nx*32*136 + (rS + jj*8)*136 + 4 + cS] = rx[jj];
            if (tid < 64) {
                int col = es ? 132 : 3;
                sB[nx*32*136 + er*136 + col] = re;
            }
#pragma unroll
            for (int jj = 0; jj < 6; jj++) {
                int i = tid + jj*256;
                int j = i >> 9, r = (i >> 3) & 63, c4 = (i & 7)*4;
                *(uint4*)&sA[nx*3*2304 + j*2304 + r*36 + c4] = rw[jj];
            }
            __syncthreads();
        }
    }
#pragma unroll
    for (int mi = 0; mi < 2; mi++) {
        int r0 = o0 + wm + mi*16 + grp;
        float bb0 = bias[r0], bb1 = bias[r0 + 8];
#pragma unroll
        for (int ni = 0; ni < 4; ni++) {
            int c0 = t0 + wn + ni*8 + qid*2;
            float v0 = acc[mi][ni][0] + bb0;
            float v1 = acc[mi][ni][1] + bb0;
            float v2 = acc[mi][ni][2] + bb1;
            float v3 = acc[mi][ni][3] + bb1;
            if (do_relu) { v0 = fmaxf(v0, 0.f); v1 = fmaxf(v1, 0.f);
                           v2 = fmaxf(v2, 0.f); v3 = fmaxf(v3, 0.f); }
            if (do_round) { v0 = rndf(v0); v1 = rndf(v1); v2 = rndf(v2); v3 = rndf(v3); }
            Ob[(size_t)r0*TT + c0]       = v0;
            Ob[(size_t)r0*TT + c0 + 1]   = v1;
            Ob[(size_t)(r0+8)*TT + c0]   = v2;
            Ob[(size_t)(r0+8)*TT + c0+1] = v3;
        }
    }
}

// ---- weight transpose+round: wt[l][j][f][c] = tf32(w[l][f][c][j]) ----------
__global__ void round_transpose_w(const float* __restrict__ w, float* __restrict__ wt,
                                  int Cout, int Cin)
{
    int idx = blockIdx.x*256 + threadIdx.x;
    int per = Cout*Cin*3;
    if (idx >= LL*per) return;
    int l = idx / per;
    int rem = idx - l*per;
    int j = rem / (Cout*Cin);
    int r2 = rem - j*Cout*Cin;
    int f = r2 / Cin, c = r2 - f*Cin;
    wt[idx] = rndf(w[((size_t)l*Cout*Cin + (size_t)f*Cin + c)*3 + j]);
}

__global__ void round_copy(const float* __restrict__ src, float* __restrict__ dst, int n)
{
    int i = blockIdx.x*256 + threadIdx.x;
    if (i < n) dst[i] = rndf(src[i]);
}

// --------- add + channel LayerNorm: Out = LN_c(X+Y)*g + beta (+rounded copy)
__global__ void add_ln_k(const float* __restrict__ X, const float* __restrict__ Y,
                         const float* __restrict__ g, const float* __restrict__ be,
                         float* __restrict__ Out, float* __restrict__ OutR)
{
    int idx = blockIdx.x*blockDim.x + threadIdx.x;
    if (idx >= BB*TT) return;
    int b = idx / TT, t = idx % TT;
    const float* xp = X + (size_t)b*CC*TT + t;
    const float* yp = Y + (size_t)b*CC*TT + t;
    float s = 0.f, sq = 0.f;
#pragma unroll 8
    for (int c = 0; c < CC; c++) {
        float v = xp[(size_t)c*TT] + yp[(size_t)c*TT];
        s += v; sq += v*v;
    }
    const float invC = 1.f / CC;
    float mean = s*invC;
    float var  = sq*invC - mean*mean;
    float rstd = rsqrtf(var + 1e-5f);
    float* op = Out + (size_t)b*CC*TT + t;
    float* orp = OutR ? OutR + (size_t)b*CC*TT + t : nullptr;
#pragma unroll 8
    for (int c = 0; c < CC; c++) {
        float v = xp[(size_t)c*TT] + yp[(size_t)c*TT];
        float o = (v - mean)*rstd*g[c] + be[c];
        op[(size_t)c*TT] = o;
        if (orp) orp[(size_t)c*TT] = rndf(o);
    }
}

// ---------------------------- host orchestration ---------------------------
extern "C" void kernel_launch(void* const* d_in, const int* in_sizes, int n_in,
                              void* d_out, int out_size)
{
    (void)in_sizes; (void)n_in; (void)out_size;
    const float* x_in = (const float*)d_in[0];
    const float* Wq = (const float*)d_in[2];
    const float* bq = (const float*)d_in[3];
    const float* Wk = (const float*)d_in[4];
    const float* bk = (const float*)d_in[5];
    const float* Wv = (const float*)d_in[6];
    const float* bv = (const float*)d_in[7];
    const float* Wo = (const float*)d_in[8];
    const float* bo = (const float*)d_in[9];
    const float* erk = (const float*)d_in[10];
    const float* erv = (const float*)d_in[11];
    const float* ln1g = (const float*)d_in[12];
    const float* ln1b = (const float*)d_in[13];
    const float* w1 = (const float*)d_in[14];
    const float* b1 = (const float*)d_in[15];
    const float* w2 = (const float*)d_in[16];
    const float* b2 = (const float*)d_in[17];
    const float* ln2g = (const float*)d_in[18];
    const float* ln2b = (const float*)d_in[19];

    float *X, *Xr, *Q, *K, *V, *A, *Y, *W1t, *W2t, *Hf, *Wqr, *Wkr, *Wvr, *Wor;
    cudaGetSymbolAddress((void**)&X,  g_X);
    cudaGetSymbolAddress((void**)&Xr, g_Xr);
    cudaGetSymbolAddress((void**)&Q,  g_Q);
    cudaGetSymbolAddress((void**)&K,  g_K);
    cudaGetSymbolAddress((void**)&V,  g_V);
    cudaGetSymbolAddress((void**)&A,  g_A);
    cudaGetSymbolAddress((void**)&Y,  g_Y);
    cudaGetSymbolAddress((void**)&W1t, g_W1t);
    cudaGetSymbolAddress((void**)&W2t, g_W2t);
    cudaGetSymbolAddress((void**)&Hf, g_Hf);
    cudaGetSymbolAddress((void**)&Wqr, g_Wqr);
    cudaGetSymbolAddress((void**)&Wkr, g_Wkr);
    cudaGetSymbolAddress((void**)&Wvr, g_Wvr);
    cudaGetSymbolAddress((void**)&Wor, g_Wor);

    const int PROJ_SMEM  = PROJ_SMEM_W*4;
    const int FLASH_SMEM = FLASH_SMEM_W*4;
    const int CONV_SMEM  = CONV_SMEM_W*4;
    cudaFuncSetAttribute(qkv_mma,   cudaFuncAttributeMaxDynamicSharedMemorySize, PROJ_SMEM);
    cudaFuncSetAttribute(proj_mma,  cudaFuncAttributeMaxDynamicSharedMemorySize, PROJ_SMEM);
    cudaFuncSetAttribute(flash_k,   cudaFuncAttributeMaxDynamicSharedMemorySize, FLASH_SMEM);
    cudaFuncSetAttribute(conv3_mma, cudaFuncAttributeMaxDynamicSharedMemorySize, CONV_SMEM);

    // one-time prep: round weights + input copy
    {
        int tot1 = LL*FCC*CC*3;
        round_transpose_w<<<(tot1 + 255)/256, 256>>>(w1, W1t, FCC, CC);
        int tot2 = LL*CC*FCC*3;
        round_transpose_w<<<(tot2 + 255)/256, 256>>>(w2, W2t, CC, FCC);
        int nw = LL*CC*CC;
        round_copy<<<(nw + 255)/256, 256>>>(Wq, Wqr, nw);
        round_copy<<<(nw + 255)/256, 256>>>(Wk, Wkr, nw);
        round_copy<<<(nw + 255)/256, 256>>>(Wv, Wvr, nw);
        round_copy<<<(nw + 255)/256, 256>>>(Wo, Wor, nw);
        int nx = BB*CC*TT;
        round_copy<<<(nx + 255)/256, 256>>>(x_in, Xr, nx);
    }

    const dim3 gqkv(9, TT/128, BB);
    const dim3 gproj(CC/64, TT/128, BB);
    const dim3 gflash(TT/64, BB*HH);
    const dim3 gc1(FCC/64, TT/128, BB);
    const dim3 gc2(CC/64, TT/128, BB);
    const int lnBlocks = (BB*TT + 255)/256;

    for (int i = 0; i < LL; i++) {
        const float* xcur = (i == 0) ? x_in : X;
        qkv_mma<<<gqkv, 256, PROJ_SMEM>>>(Wqr + (size_t)i*CC*CC, bq + i*CC,
                                          Wkr + (size_t)i*CC*CC, bk + i*CC,
                                          Wvr + (size_t)i*CC*CC, bv + i*CC,
                                          Xr, Q, K, V);
        flash_k<<<gflash, 256, FLASH_SMEM>>>(Q, K, V,
                                             erk + (size_t)i*9*DKK,
                                             erv + (size_t)i*9*DKK, A);
        proj_mma<<<gproj, 256, PROJ_SMEM>>>(Wor + (size_t)i*CC*CC, bo + i*CC, A, Y);
        add_ln_k<<<lnBlocks, 256>>>(xcur, Y, ln1g + i*CC, ln1b + i*CC, X, Xr);
        conv3_mma<<<gc1, 256, CONV_SMEM>>>(W1t + (size_t)i*3*FCC*CC, b1 + i*FCC,
                                           Xr, Hf, FCC, CC, 1, 1);
        conv3_mma<<<gc2, 256, CONV_SMEM>>>(W2t + (size_t)i*3*CC*FCC, b2 + i*CC,
                                           Hf, Y, CC, FCC, 0, 0);
        add_ln_k<<<lnBlocks, 256>>>(X, Y, ln2g + i*CC, ln2b + i*CC,
                                    (i == LL-1) ? (float*)d_out : X,
                                    (i == LL-1) ? nullptr : Xr);
    }
}